// round 2
// baseline (speedup 1.0000x reference)
#include <cuda_runtime.h>

// Problem constants
#define N_IMG 16384
#define SS 49
#define NCELL (N_IMG * SS)          // 802816
#define F 30                        // 20 probs + 2 conf + 8 box
#define CPB 128                     // cells per block
#define NBLK (NCELL / CPB)          // 6272

__device__ float g_partial[NBLK];
__device__ unsigned int g_count;    // zero-init at load; last block resets to 0 each run

__global__ __launch_bounds__(CPB) void loss_kernel(const float* __restrict__ preds,
                                                   const float* __restrict__ targets,
                                                   float* __restrict__ out) {
    __shared__ float sp[CPB * F];
    __shared__ float st[CPB * F];
    __shared__ float warp_sums[CPB / 32];
    __shared__ bool is_last;

    const long long base = (long long)blockIdx.x * (CPB * F);

    // Cooperative coalesced float4 staging. Chunk base is 30720*blockIdx bytes,
    // 16B-aligned; CPB*F = 3840 floats = 960 float4 per tensor.
    const float4* __restrict__ p4 = reinterpret_cast<const float4*>(preds + base);
    const float4* __restrict__ t4 = reinterpret_cast<const float4*>(targets + base);
    float4* sp4 = reinterpret_cast<float4*>(sp);
    float4* st4 = reinterpret_cast<float4*>(st);
    const int n4 = CPB * F / 4;  // 960
#pragma unroll
    for (int i = threadIdx.x; i < n4; i += CPB) {
        sp4[i] = p4[i];
        st4[i] = t4[i];
    }
    __syncthreads();

    const float* p = sp + threadIdx.x * F;
    const float* t = st + threadIdx.x * F;

    // conf MSE term (always): NOOBJ * sum((p_conf - t_conf)^2)
    float pc0 = p[20], pc1 = p[21];
    float tc0 = t[20], tc1 = t[21];
    float d0 = pc0 - tc0, d1 = pc1 - tc1;
    float l = 0.5f * (d0 * d0 + d1 * d1);

    if (tc0 > 0.0f) {  // obj cell
        // class-prob MSE
        float s = 0.0f;
#pragma unroll
        for (int c = 0; c < 20; c++) {
            float d = p[c] - t[c];
            s += d * d;
        }
        l += s;

        // IoU of both predicted boxes vs target boxes
        float iou0, iou1;
#pragma unroll
        for (int b = 0; b < 2; b++) {
            const float* pb = p + 22 + 4 * b;
            const float* tb = t + 22 + 4 * b;
            float xA = fmaxf(pb[0] - pb[2] * 0.5f, tb[0] - tb[2] * 0.5f);
            float yA = fmaxf(pb[1] - pb[3] * 0.5f, tb[1] - tb[3] * 0.5f);
            float xB = fminf(pb[0] + pb[2] * 0.5f, tb[0] + tb[2] * 0.5f);
            float yB = fminf(pb[1] + pb[3] * 0.5f, tb[1] + tb[3] * 0.5f);
            float inter = fmaxf(0.0f, xB - xA) * fmaxf(0.0f, yB - yA);
            float areaA = pb[2] * pb[3];
            float areaB = tb[2] * tb[3];
            float iou = inter / (areaA + areaB - inter);
            if (b == 0) iou0 = iou; else iou1 = iou;
        }
        int best = (iou1 > iou0) ? 1 : 0;  // argmax, tie -> index 0

        // responsible-box confidence term: (1 - NOOBJ) * (pc - 1)^2
        float pc = best ? pc1 : pc0;
        float dc = pc - 1.0f;
        l += 0.5f * dc * dc;

        // coord term
        const float* pb = p + 22 + 4 * best;
        const float* tb = t + 22 + 4 * best;
        float dx = pb[0] - tb[0];
        float dy = pb[1] - tb[1];
        float dw = sqrtf(pb[2]) - sqrtf(tb[2]);
        float dh = sqrtf(pb[3]) - sqrtf(tb[3]);
        l += 5.0f * (dx * dx + dy * dy + dw * dw + dh * dh);
    }

    // intra-block reduction
#pragma unroll
    for (int off = 16; off > 0; off >>= 1)
        l += __shfl_down_sync(0xffffffffu, l, off);
    if ((threadIdx.x & 31) == 0)
        warp_sums[threadIdx.x >> 5] = l;
    __syncthreads();

    if (threadIdx.x == 0) {
        float blk = warp_sums[0] + warp_sums[1] + warp_sums[2] + warp_sums[3];
        g_partial[blockIdx.x] = blk;
        __threadfence();
        unsigned int old = atomicAdd(&g_count, 1u);
        is_last = (old == NBLK - 1);
    }
    __syncthreads();

    // Last block to finish: reduce all partials, write result, reset counter.
    if (is_last) {
        double acc = 0.0;
        for (int i = threadIdx.x; i < NBLK; i += CPB)
            acc += (double)__ldcg(&g_partial[i]);

        // reduce doubles across the block
        __shared__ double dsum[CPB / 32];
#pragma unroll
        for (int off = 16; off > 0; off >>= 1)
            acc += __shfl_down_sync(0xffffffffu, acc, off);
        if ((threadIdx.x & 31) == 0)
            dsum[threadIdx.x >> 5] = acc;
        __syncthreads();
        if (threadIdx.x == 0) {
            double total = dsum[0] + dsum[1] + dsum[2] + dsum[3];
            out[0] = (float)(total / (double)N_IMG);
            __threadfence();
            g_count = 0;  // reset for next graph replay
        }
    }
}

extern "C" void kernel_launch(void* const* d_in, const int* in_sizes, int n_in,
                              void* d_out, int out_size) {
    const float* preds = (const float*)d_in[0];
    const float* targets = (const float*)d_in[1];
    float* out = (float*)d_out;

    loss_kernel<<<NBLK, CPB>>>(preds, targets, out);
}

// round 3
// speedup vs baseline: 1.3904x; 1.3904x over previous
#include <cuda_runtime.h>
#include <cstdint>

// Problem constants
#define N_IMG 16384
#define SS 49
#define NCELL (N_IMG * SS)            // 802816
#define F 30                          // 20 probs + 2 conf + 8 box
#define CPC 128                       // cells per chunk
#define NCHUNK (NCELL / CPC)          // 6272
#define THREADS 128
#define GRID 444                      // 3 blocks/SM * 148 SMs

#define CHUNK_FLOATS (CPC * F)        // 3840 floats
#define CHUNK_BYTES (CHUNK_FLOATS * 4)  // 15360 B per tensor
#define TX_BYTES (2 * CHUNK_BYTES)      // 30720 B per chunk
#define DYN_SMEM (2 * TX_BYTES)         // 61440 B (double buffer)

__device__ float g_partial[GRID];
__device__ unsigned int g_count;      // zero at load; last block resets each run

__device__ __forceinline__ uint32_t smem_u32(const void* p) {
    return (uint32_t)__cvta_generic_to_shared(p);
}

#define MBAR_WAIT(bar, parity) do {                                           \
    asm volatile(                                                             \
        "{\n\t.reg .pred P1;\n\t"                                             \
        "WAIT_%=:\n\t"                                                        \
        "mbarrier.try_wait.parity.acquire.cta.shared::cta.b64 P1, [%0], %1, 0x989680;\n\t" \
        "@P1 bra.uni DONE_%=;\n\t"                                            \
        "bra.uni WAIT_%=;\n\t"                                                \
        "DONE_%=:\n\t}"                                                       \
        :: "r"(bar), "r"(parity) : "memory");                                 \
} while (0)

__global__ __launch_bounds__(THREADS) void loss_kernel(
        const float* __restrict__ preds,
        const float* __restrict__ targets,
        float* __restrict__ out) {
    extern __shared__ float smem[];   // [2 buffers][preds 3840 | targets 3840]
    __shared__ __align__(8) unsigned long long mbar[2];
    __shared__ float warp_sums[THREADS / 32];
    __shared__ double dsum[THREADS / 32];
    __shared__ bool is_last;

    const int tid = threadIdx.x;

    if (tid == 0) {
        asm volatile("mbarrier.init.shared.b64 [%0], 1;"
                     :: "r"(smem_u32(&mbar[0])) : "memory");
        asm volatile("mbarrier.init.shared.b64 [%0], 1;"
                     :: "r"(smem_u32(&mbar[1])) : "memory");
    }
    __syncthreads();

    // Issue one chunk's loads (both tensors) into buffer `buf`.
    auto issue = [&](int c, int buf) {
        uint32_t bar = smem_u32(&mbar[buf]);
        asm volatile("mbarrier.arrive.expect_tx.shared.b64 _, [%0], %1;"
                     :: "r"(bar), "r"((uint32_t)TX_BYTES) : "memory");
        uint32_t dstp = smem_u32(smem) + buf * TX_BYTES;
        uint32_t dstt = dstp + CHUNK_BYTES;
        const float* srcp = preds + (long long)c * CHUNK_FLOATS;
        const float* srct = targets + (long long)c * CHUNK_FLOATS;
        asm volatile("cp.async.bulk.shared::cta.global.mbarrier::complete_tx::bytes [%0], [%1], %2, [%3];"
                     :: "r"(dstp), "l"(srcp), "r"((uint32_t)CHUNK_BYTES), "r"(bar) : "memory");
        asm volatile("cp.async.bulk.shared::cta.global.mbarrier::complete_tx::bytes [%0], [%1], %2, [%3];"
                     :: "r"(dstt), "l"(srct), "r"((uint32_t)CHUNK_BYTES), "r"(bar) : "memory");
    };

    // Prologue: prefetch first two chunks.
    if (tid == 0) {
        if ((int)blockIdx.x < NCHUNK) issue(blockIdx.x, 0);
        if ((int)blockIdx.x + GRID < NCHUNK) issue(blockIdx.x + GRID, 1);
    }

    float l = 0.0f;
    int k = 0;
    for (int c = blockIdx.x; c < NCHUNK; c += GRID, k++) {
        const int buf = k & 1;
        const int phs = (k >> 1) & 1;
        MBAR_WAIT(smem_u32(&mbar[buf]), phs);

        const float* p = smem + buf * 2 * CHUNK_FLOATS + tid * F;
        const float* t = p + CHUNK_FLOATS;

        // conf MSE term (always): NOOBJ * sum((p_conf - t_conf)^2)
        float pc0 = p[20], pc1 = p[21];
        float tc0 = t[20], tc1 = t[21];
        float d0 = pc0 - tc0, d1 = pc1 - tc1;
        l += 0.5f * (d0 * d0 + d1 * d1);

        if (tc0 > 0.0f) {  // obj cell
            float s = 0.0f;
#pragma unroll
            for (int cc = 0; cc < 20; cc++) {
                float d = p[cc] - t[cc];
                s += d * d;
            }
            l += s;

            float iou0, iou1;
#pragma unroll
            for (int b = 0; b < 2; b++) {
                const float* pb = p + 22 + 4 * b;
                const float* tb = t + 22 + 4 * b;
                float xA = fmaxf(pb[0] - pb[2] * 0.5f, tb[0] - tb[2] * 0.5f);
                float yA = fmaxf(pb[1] - pb[3] * 0.5f, tb[1] - tb[3] * 0.5f);
                float xB = fminf(pb[0] + pb[2] * 0.5f, tb[0] + tb[2] * 0.5f);
                float yB = fminf(pb[1] + pb[3] * 0.5f, tb[1] + tb[3] * 0.5f);
                float inter = fmaxf(0.0f, xB - xA) * fmaxf(0.0f, yB - yA);
                float areaA = pb[2] * pb[3];
                float areaB = tb[2] * tb[3];
                float iou = inter / (areaA + areaB - inter);
                if (b == 0) iou0 = iou; else iou1 = iou;
            }
            int best = (iou1 > iou0) ? 1 : 0;  // argmax, tie -> index 0

            float pc = best ? pc1 : pc0;
            float dc = pc - 1.0f;
            l += 0.5f * dc * dc;

            const float* pb = p + 22 + 4 * best;
            const float* tb = t + 22 + 4 * best;
            float dx = pb[0] - tb[0];
            float dy = pb[1] - tb[1];
            float dw = sqrtf(pb[2]) - sqrtf(tb[2]);
            float dh = sqrtf(pb[3]) - sqrtf(tb[3]);
            l += 5.0f * (dx * dx + dy * dy + dw * dw + dh * dh);
        }

        __syncthreads();  // all threads done reading buffer `buf`

        int nx = c + 2 * GRID;
        if (tid == 0 && nx < NCHUNK) issue(nx, buf);
    }

    // Intra-block reduction (once, at the very end).
#pragma unroll
    for (int off = 16; off > 0; off >>= 1)
        l += __shfl_down_sync(0xffffffffu, l, off);
    if ((tid & 31) == 0)
        warp_sums[tid >> 5] = l;
    __syncthreads();

    if (tid == 0) {
        float blk = warp_sums[0] + warp_sums[1] + warp_sums[2] + warp_sums[3];
        g_partial[blockIdx.x] = blk;
        __threadfence();
        unsigned int old = atomicAdd(&g_count, 1u);
        is_last = (old == GRID - 1);
    }
    __syncthreads();

    if (is_last) {
        double acc = 0.0;
        for (int i = tid; i < GRID; i += THREADS)
            acc += (double)__ldcg(&g_partial[i]);
#pragma unroll
        for (int off = 16; off > 0; off >>= 1)
            acc += __shfl_down_sync(0xffffffffu, acc, off);
        if ((tid & 31) == 0)
            dsum[tid >> 5] = acc;
        __syncthreads();
        if (tid == 0) {
            double total = dsum[0] + dsum[1] + dsum[2] + dsum[3];
            out[0] = (float)(total / (double)N_IMG);
            __threadfence();
            g_count = 0;  // reset for next graph replay
        }
    }
}

extern "C" void kernel_launch(void* const* d_in, const int* in_sizes, int n_in,
                              void* d_out, int out_size) {
    const float* preds = (const float*)d_in[0];
    const float* targets = (const float*)d_in[1];
    float* out = (float*)d_out;

    cudaFuncSetAttribute(loss_kernel, cudaFuncAttributeMaxDynamicSharedMemorySize, DYN_SMEM);
    loss_kernel<<<GRID, THREADS, DYN_SMEM>>>(preds, targets, out);
}